// round 1
// baseline (speedup 1.0000x reference)
#include <cuda_runtime.h>
#include <math.h>

#define TB 4
#define TT 2048
#define TE 512
#define TH 8
#define TD 64
#define TBH 32
#define TU 40
#define TM 8192
#define NSPLIT 8

// ---------------- scratch (static device globals; no allocation) ----------------
__device__ float g_q[TBH*TT*TD];        // 16 MB  split-head, pre-scaled
__device__ float g_k[TBH*TT*TD];        // 16 MB
__device__ float g_v[TBH*TT*TD];        // 16 MB
__device__ float g_ks[TBH*TT*TD];       // 16 MB  gathered k_sample (packed)
__device__ float g_ksum[TBH*TD];
__device__ float g_vmean[TBH*TD];
__device__ float g_sp[TBH*TT];          // sparsity scores
__device__ int   g_top[TBH*TU];
__device__ float g_sc[TBH*TU*TT];       // scores -> probs (in place)
__device__ float g_part[TBH*NSPLIT*TU*TD];
__device__ float g_ctx[TM*TE];          // 16 MB  merged context

// =====================================================================
// Kernel 1: fused QKV projection.  out = (hs @ W^T + b) [*scale]
// M=8192 N=512 K=512, NT gemm, 128x128x16 tile, 8x8 per thread.
// Writes directly into split-head layout [bh][t][d].
// =====================================================================
__global__ __launch_bounds__(256) void qkv_gemm(
    const float* __restrict__ hs,
    const float* __restrict__ Wq, const float* __restrict__ bq,
    const float* __restrict__ Wk, const float* __restrict__ bk,
    const float* __restrict__ Wv, const float* __restrict__ bv)
{
    __shared__ float As[16][132];
    __shared__ float Bs[16][132];
    const int which = blockIdx.z;
    const float* W    = (which == 0) ? Wq : (which == 1) ? Wk : Wv;
    const float* bias = (which == 0) ? bq : (which == 1) ? bk : bv;
    float* out        = (which == 0) ? g_q : (which == 1) ? g_k : g_v;
    const float scale = (which == 0) ? 0.125f : 1.0f;   // HEAD_DIM^-0.5

    const int tid = threadIdx.x;
    const int tx = tid & 15, ty = tid >> 4;
    const int m0 = blockIdx.y * 128, n0 = blockIdx.x * 128;

    float acc[8][8];
#pragma unroll
    for (int r = 0; r < 8; r++)
#pragma unroll
        for (int c = 0; c < 8; c++) acc[r][c] = 0.f;

    for (int kt = 0; kt < 512; kt += 16) {
#pragma unroll
        for (int i = 0; i < 2; i++) {
            int l = tid + i * 256;
            int row = l >> 2, kq = l & 3;
            float4 a = *(const float4*)&hs[(m0 + row) * 512 + kt + kq * 4];
            As[kq*4+0][row] = a.x; As[kq*4+1][row] = a.y;
            As[kq*4+2][row] = a.z; As[kq*4+3][row] = a.w;
            float4 b = *(const float4*)&W[(n0 + row) * 512 + kt + kq * 4];
            Bs[kq*4+0][row] = b.x; Bs[kq*4+1][row] = b.y;
            Bs[kq*4+2][row] = b.z; Bs[kq*4+3][row] = b.w;
        }
        __syncthreads();
#pragma unroll
        for (int k = 0; k < 16; k++) {
            float4 a0 = *(const float4*)&As[k][ty*8];
            float4 a1 = *(const float4*)&As[k][ty*8+4];
            float4 b0 = *(const float4*)&Bs[k][tx*8];
            float4 b1 = *(const float4*)&Bs[k][tx*8+4];
            float ar[8] = {a0.x,a0.y,a0.z,a0.w,a1.x,a1.y,a1.z,a1.w};
            float br[8] = {b0.x,b0.y,b0.z,b0.w,b1.x,b1.y,b1.z,b1.w};
#pragma unroll
            for (int r = 0; r < 8; r++)
#pragma unroll
                for (int c = 0; c < 8; c++)
                    acc[r][c] = fmaf(ar[r], br[c], acc[r][c]);
        }
        __syncthreads();
    }

    // epilogue: split heads, add bias, scale q
    const int n = n0 + tx * 8;
    const int h = n >> 6, d0 = n & 63;   // 8 cols never cross a head boundary
#pragma unroll
    for (int r = 0; r < 8; r++) {
        int m = m0 + ty * 8 + r;
        int b = m >> 11, t = m & 2047;
        float* orow = &out[(((b << 3) + h) * 2048 + t) * 64 + d0];
        float4 o0, o1;
        o0.x = (acc[r][0] + bias[n+0]) * scale;
        o0.y = (acc[r][1] + bias[n+1]) * scale;
        o0.z = (acc[r][2] + bias[n+2]) * scale;
        o0.w = (acc[r][3] + bias[n+3]) * scale;
        o1.x = (acc[r][4] + bias[n+4]) * scale;
        o1.y = (acc[r][5] + bias[n+5]) * scale;
        o1.z = (acc[r][6] + bias[n+6]) * scale;
        o1.w = (acc[r][7] + bias[n+7]) * scale;
        *(float4*)&orow[0] = o0;
        *(float4*)&orow[4] = o1;
    }
}

// =====================================================================
// Kernel 2: gather sampled keys into packed buffer (per bh)
// =====================================================================
__global__ __launch_bounds__(256) void gather_kernel(const int* __restrict__ idx)
{
    const int bh = blockIdx.x, jb = blockIdx.y, tid = threadIdx.x;
#pragma unroll 4
    for (int it = 0; it < 16; it++) {
        int l = it * 256 + tid;
        int jl = l >> 4, q4 = l & 15;
        int j = jb * 256 + jl;
        int ti = idx[j];
        *(float4*)&g_ks[(bh * 2048 + j) * 64 + q4 * 4] =
            *(const float4*)&g_k[(bh * 2048 + ti) * 64 + q4 * 4];
    }
}

// =====================================================================
// Kernel 3: ksum (sum over sampled keys) and vmean
// =====================================================================
__global__ void stats_kernel()
{
    const int bh = blockIdx.x, d = threadIdx.x;   // 64 threads
    if (blockIdx.y == 0) {
        float s = 0.f;
        for (int j = 0; j < 2048; j++) s += g_ks[(bh * 2048 + j) * 64 + d];
        g_ksum[bh * 64 + d] = s;
    } else {
        float s = 0.f;
        for (int j = 0; j < 2048; j++) s += g_v[(bh * 2048 + j) * 64 + d];
        g_vmean[bh * 64 + d] = s * (1.0f / 2048.0f);
    }
}

// =====================================================================
// Kernel 4: sparsity = rowmax(q @ ks^T) - (q . ksum)/2048
// Fused max-epilogue GEMM: per CTA 128 q-rows x all 2048 sampled keys.
// =====================================================================
__global__ __launch_bounds__(256) void sparsity_kernel()
{
    __shared__ float As[16][132];
    __shared__ float Bs[16][132];
    __shared__ float red[128][17];
    __shared__ float sks[64];
    const int bh = blockIdx.y;
    const int m0 = blockIdx.x * 128;
    const int tid = threadIdx.x, tx = tid & 15, ty = tid >> 4;
    const float* A  = g_q  + bh * TT * TD;
    const float* Bm = g_ks + bh * TT * TD;

    float rmax[8];
#pragma unroll
    for (int r = 0; r < 8; r++) rmax[r] = -INFINITY;

    for (int nt = 0; nt < 16; nt++) {
        const int n0 = nt * 128;
        float acc[8][8];
#pragma unroll
        for (int r = 0; r < 8; r++)
#pragma unroll
            for (int c = 0; c < 8; c++) acc[r][c] = 0.f;

        for (int kt = 0; kt < 64; kt += 16) {
#pragma unroll
            for (int i = 0; i < 2; i++) {
                int l = tid + i * 256;
                int row = l >> 2, kq = l & 3;
                float4 a = *(const float4*)&A[(m0 + row) * 64 + kt + kq * 4];
                As[kq*4+0][row] = a.x; As[kq*4+1][row] = a.y;
                As[kq*4+2][row] = a.z; As[kq*4+3][row] = a.w;
                float4 b = *(const float4*)&Bm[(n0 + row) * 64 + kt + kq * 4];
                Bs[kq*4+0][row] = b.x; Bs[kq*4+1][row] = b.y;
                Bs[kq*4+2][row] = b.z; Bs[kq*4+3][row] = b.w;
            }
            __syncthreads();
#pragma unroll
            for (int k = 0; k < 16; k++) {
                float4 a0 = *(const float4*)&As[k][ty*8];
                float4 a1 = *(const float4*)&As[k][ty*8+4];
                float4 b0 = *(const float4*)&Bs[k][tx*8];
                float4 b1 = *(const float4*)&Bs[k][tx*8+4];
                float ar[8] = {a0.x,a0.y,a0.z,a0.w,a1.x,a1.y,a1.z,a1.w};
                float br[8] = {b0.x,b0.y,b0.z,b0.w,b1.x,b1.y,b1.z,b1.w};
#pragma unroll
                for (int r = 0; r < 8; r++)
#pragma unroll
                    for (int c = 0; c < 8; c++)
                        acc[r][c] = fmaf(ar[r], br[c], acc[r][c]);
            }
            __syncthreads();
        }
#pragma unroll
        for (int r = 0; r < 8; r++)
#pragma unroll
            for (int c = 0; c < 8; c++)
                rmax[r] = fmaxf(rmax[r], acc[r][c]);
    }

#pragma unroll
    for (int r = 0; r < 8; r++) red[ty * 8 + r][tx] = rmax[r];
    if (tid < 64) sks[tid] = g_ksum[bh * 64 + tid];
    __syncthreads();

    if (tid < 128) {
        float m = -INFINITY;
#pragma unroll
        for (int x = 0; x < 16; x++) m = fmaxf(m, red[tid][x]);
        const float* qr = A + (m0 + tid) * 64;
        float dot = 0.f;
#pragma unroll
        for (int d = 0; d < 64; d++) dot = fmaf(qr[d], sks[d], dot);
        g_sp[bh * TT + m0 + tid] = m - dot * (1.0f / 2048.0f);
    }
}

// =====================================================================
// Kernel 5: deterministic top-40 per bh (iterative block argmax,
// lower index wins ties — matches jax.lax.top_k selection set)
// =====================================================================
__global__ __launch_bounds__(256) void topk_kernel()
{
    __shared__ float sp[2048];
    __shared__ float rv[256];
    __shared__ int   ri[256];
    const int bh = blockIdx.x, tid = threadIdx.x;
    for (int l = tid; l < 2048; l += 256) sp[l] = g_sp[bh * 2048 + l];
    __syncthreads();
    for (int it = 0; it < TU; it++) {
        float bv = -INFINITY; int bi = 2048;
        for (int l = tid; l < 2048; l += 256) {
            float v = sp[l];
            if (v > bv) { bv = v; bi = l; }
        }
        rv[tid] = bv; ri[tid] = bi;
        __syncthreads();
        for (int s = 128; s > 0; s >>= 1) {
            if (tid < s) {
                float ov = rv[tid + s]; int oi = ri[tid + s];
                if (ov > rv[tid] || (ov == rv[tid] && oi < ri[tid])) { rv[tid] = ov; ri[tid] = oi; }
            }
            __syncthreads();
        }
        if (tid == 0) { g_top[bh * TU + it] = ri[0]; sp[ri[0]] = -INFINITY; }
        __syncthreads();
    }
}

// =====================================================================
// Kernel 6: scores = q_reduce @ k^T  -> g_sc [bh][40][2048]
// =====================================================================
__global__ __launch_bounds__(256) void scores_kernel()
{
    __shared__ float qs[40][68];
    __shared__ float ks[128][68];
    const int nt = blockIdx.x, bh = blockIdx.y, tid = threadIdx.x;
    const int n0 = nt * 128;
    for (int l = tid; l < 640; l += 256) {
        int i = l >> 4, q4 = l & 15;
        int t = g_top[bh * TU + i];
        *(float4*)&qs[i][q4*4] = *(const float4*)&g_q[(bh * 2048 + t) * 64 + q4 * 4];
    }
    for (int l = tid; l < 2048; l += 256) {
        int j = l >> 4, q4 = l & 15;
        *(float4*)&ks[j][q4*4] = *(const float4*)&g_k[(bh * 2048 + n0 + j) * 64 + q4 * 4];
    }
    __syncthreads();
    const int j = tid & 127;
    const int i0 = (tid >> 7) * 20;
    for (int i = i0; i < i0 + 20; i++) {
        float dot = 0.f;
#pragma unroll
        for (int d = 0; d < 64; d++) dot = fmaf(qs[i][d], ks[j][d], dot);
        g_sc[(bh * TU + i) * 2048 + n0 + j] = dot;
    }
}

// =====================================================================
// Kernel 7: row softmax over 2048 (in place)
// =====================================================================
__global__ __launch_bounds__(256) void softmax_kernel()
{
    __shared__ float red[256];
    const int row = blockIdx.x, tid = threadIdx.x;
    float* p = g_sc + row * 2048;
    float m = -INFINITY;
    for (int l = tid; l < 2048; l += 256) m = fmaxf(m, p[l]);
    red[tid] = m; __syncthreads();
    for (int s = 128; s > 0; s >>= 1) { if (tid < s) red[tid] = fmaxf(red[tid], red[tid + s]); __syncthreads(); }
    m = red[0]; __syncthreads();
    float sum = 0.f;
    for (int l = tid; l < 2048; l += 256) {
        float e = expf(p[l] - m);
        p[l] = e;
        sum += e;
    }
    red[tid] = sum; __syncthreads();
    for (int s = 128; s > 0; s >>= 1) { if (tid < s) red[tid] += red[tid + s]; __syncthreads(); }
    const float inv = 1.0f / red[0];
    for (int l = tid; l < 2048; l += 256) p[l] *= inv;
}

// =====================================================================
// Kernel 8: attn_out partials = probs @ v  (split over 8 key ranges)
// =====================================================================
__global__ __launch_bounds__(256) void pv_kernel()
{
    __shared__ float vs[64][68];
    __shared__ float ps[40][68];
    const int sp = blockIdx.x, bh = blockIdx.y, tid = threadIdx.x;
    const int d = tid & 63, ig = tid >> 6;
    float acc[10];
#pragma unroll
    for (int s = 0; s < 10; s++) acc[s] = 0.f;
    for (int c = 0; c < 4; c++) {
        const int j0 = sp * 256 + c * 64;
        for (int l = tid; l < 1024; l += 256) {
            int j = l >> 4, q4 = l & 15;
            *(float4*)&vs[j][q4*4] = *(const float4*)&g_v[(bh * 2048 + j0 + j) * 64 + q4 * 4];
        }
        for (int l = tid; l < 640; l += 256) {
            int i = l >> 4, q4 = l & 15;
            *(float4*)&ps[i][q4*4] = *(const float4*)&g_sc[(bh * TU + i) * 2048 + j0 + q4 * 4];
        }
        __syncthreads();
#pragma unroll 4
        for (int jj = 0; jj < 64; jj++) {
            float vv = vs[jj][d];
#pragma unroll
            for (int s = 0; s < 10; s++)
                acc[s] = fmaf(ps[ig * 10 + s][jj], vv, acc[s]);
        }
        __syncthreads();
    }
#pragma unroll
    for (int s = 0; s < 10; s++)
        g_part[((bh * NSPLIT + sp) * TU + ig * 10 + s) * 64 + d] = acc[s];
}

// =====================================================================
// Kernel 9: fill merged context with broadcast vmean
// =====================================================================
__global__ __launch_bounds__(256) void ctxfill_kernel()
{
    const int idx = blockIdx.x * 256 + threadIdx.x;    // 1,048,576 float4s
    const int m = idx >> 7, nf4 = idx & 127;
    const int b = m >> 11;
    const int h = nf4 >> 4, d0 = (nf4 & 15) * 4;
    float4 v = *(const float4*)&g_vmean[((b << 3) + h) * 64 + d0];
    *(float4*)&g_ctx[m * 512 + nf4 * 4] = v;
}

// =====================================================================
// Kernel 10: reduce attn partials and scatter into context rows
// (top_idx unique within a head; heads write disjoint columns -> no races)
// =====================================================================
__global__ void scatter_kernel()
{
    const int bh = blockIdx.x, i = blockIdx.y, d = threadIdx.x;  // 64 threads
    const int t = g_top[bh * TU + i];
    float s = 0.f;
#pragma unroll
    for (int sp = 0; sp < NSPLIT; sp++)
        s += g_part[((bh * NSPLIT + sp) * TU + i) * 64 + d];
    const int b = bh >> 3, h = bh & 7;
    g_ctx[((b << 11) + t) * 512 + (h << 6) + d] = s;
}

// =====================================================================
// Kernel 11: output projection  out = ctx @ Wo^T + bo
// =====================================================================
__global__ __launch_bounds__(256) void out_gemm(
    const float* __restrict__ Wo, const float* __restrict__ bo,
    float* __restrict__ out)
{
    __shared__ float As[16][132];
    __shared__ float Bs[16][132];
    const int tid = threadIdx.x;
    const int tx = tid & 15, ty = tid >> 4;
    const int m0 = blockIdx.y * 128, n0 = blockIdx.x * 128;

    float acc[8][8];
#pragma unroll
    for (int r = 0; r < 8; r++)
#pragma unroll
        for (int c = 0; c < 8; c++) acc[r][c] = 0.f;

    for (int kt = 0; kt < 512; kt += 16) {
#pragma unroll
        for (int i = 0; i < 2; i++) {
            int l = tid + i * 256;
            int row = l >> 2, kq = l & 3;
            float4 a = *(const float4*)&g_ctx[(m0 + row) * 512 + kt + kq * 4];
            As[kq*4+0][row] = a.x; As[kq*4+1][row] = a.y;
            As[kq*4+2][row] = a.z; As[kq*4+3][row] = a.w;
            float4 b = *(const float4*)&Wo[(n0 + row) * 512 + kt + kq * 4];
            Bs[kq*4+0][row] = b.x; Bs[kq*4+1][row] = b.y;
            Bs[kq*4+2][row] = b.z; Bs[kq*4+3][row] = b.w;
        }
        __syncthreads();
#pragma unroll
        for (int k = 0; k < 16; k++) {
            float4 a0 = *(const float4*)&As[k][ty*8];
            float4 a1 = *(const float4*)&As[k][ty*8+4];
            float4 b0 = *(const float4*)&Bs[k][tx*8];
            float4 b1 = *(const float4*)&Bs[k][tx*8+4];
            float ar[8] = {a0.x,a0.y,a0.z,a0.w,a1.x,a1.y,a1.z,a1.w};
            float br[8] = {b0.x,b0.y,b0.z,b0.w,b1.x,b1.y,b1.z,b1.w};
#pragma unroll
            for (int r = 0; r < 8; r++)
#pragma unroll
                for (int c = 0; c < 8; c++)
                    acc[r][c] = fmaf(ar[r], br[c], acc[r][c]);
        }
        __syncthreads();
    }

    const int n = n0 + tx * 8;
#pragma unroll
    for (int r = 0; r < 8; r++) {
        int m = m0 + ty * 8 + r;
        float4 o0, o1;
        o0.x = acc[r][0] + bo[n+0]; o0.y = acc[r][1] + bo[n+1];
        o0.z = acc[r][2] + bo[n+2]; o0.w = acc[r][3] + bo[n+3];
        o1.x = acc[r][4] + bo[n+4]; o1.y = acc[r][5] + bo[n+5];
        o1.z = acc[r][6] + bo[n+6]; o1.w = acc[r][7] + bo[n+7];
        *(float4*)&out[m * 512 + n]     = o0;
        *(float4*)&out[m * 512 + n + 4] = o1;
    }
}

// =====================================================================
extern "C" void kernel_launch(void* const* d_in, const int* in_sizes, int n_in,
                              void* d_out, int out_size)
{
    const float* hs = (const float*)d_in[0];
    const int*  idx = (const int*)  d_in[1];
    const float* Wq = (const float*)d_in[2]; const float* bq = (const float*)d_in[3];
    const float* Wk = (const float*)d_in[4]; const float* bk = (const float*)d_in[5];
    const float* Wv = (const float*)d_in[6]; const float* bv = (const float*)d_in[7];
    const float* Wo = (const float*)d_in[8]; const float* bo = (const float*)d_in[9];
    float* out = (float*)d_out;

    qkv_gemm   <<<dim3(4, 64, 3), 256>>>(hs, Wq, bq, Wk, bk, Wv, bv);
    gather_kernel<<<dim3(32, 8), 256>>>(idx);
    stats_kernel <<<dim3(32, 2), 64>>>();
    sparsity_kernel<<<dim3(16, 32), 256>>>();
    topk_kernel  <<<32, 256>>>();
    scores_kernel<<<dim3(16, 32), 256>>>();
    softmax_kernel<<<TBH * TU, 256>>>();
    pv_kernel    <<<dim3(NSPLIT, 32), 256>>>();
    ctxfill_kernel<<<4096, 256>>>();
    scatter_kernel<<<dim3(32, TU), 64>>>();
    out_gemm     <<<dim3(4, 64), 256>>>(Wo, bo, out);
}

// round 10
// speedup vs baseline: 1.1968x; 1.1968x over previous
#include <cuda_runtime.h>
#include <cuda_bf16.h>
#include <math.h>
#include <stdint.h>

#define TB 4
#define TT 2048
#define TE 512
#define TH 8
#define TD 64
#define TBH 32
#define TU 40
#define TCAP 256
#define TM 8192
#define NSPLIT 8

// ---------------- scratch ----------------
__device__ float g_q[TBH*TT*TD];
__device__ float g_k[TBH*TT*TD];
__device__ float g_v[TBH*TT*TD];
__device__ float g_ks[TBH*TT*TD];
__device__ __nv_bfloat16 g_qh[TBH*TT*TD];
__device__ __nv_bfloat16 g_ql[TBH*TT*TD];
__device__ __nv_bfloat16 g_kh[TBH*TT*TD];
__device__ __nv_bfloat16 g_kl[TBH*TT*TD];
__device__ float g_ksum[TBH*TD];
__device__ float g_vmean[TBH*TD];
__device__ float g_sp[TBH*TT];        // approximate sparsity (prefilter only)
__device__ float g_s40[TBH];          // approx 40th-largest sparsity
__device__ int   g_cand[TBH*TCAP];
__device__ int   g_ncand[TBH];
__device__ float g_rmax[TBH*TCAP*NSPLIT];
__device__ int   g_top[TBH*TU];
__device__ float g_sc[TBH*TU*TT];
__device__ float g_part[TBH*NSPLIT*TU*TD];
__device__ float g_ctx[TM*TE];

// ---------------- helpers ----------------
__device__ __forceinline__ uint32_t smem_u32(const void* p) {
    uint32_t a;
    asm("{ .reg .u64 t; cvta.to.shared.u64 t, %1; cvt.u32.u64 %0, t; }" : "=r"(a) : "l"(p));
    return a;
}

#define LDSM_X4(r, addr) \
    asm volatile("ldmatrix.sync.aligned.m8n8.x4.shared.b16 {%0,%1,%2,%3}, [%4];" \
        : "=r"((r)[0]),"=r"((r)[1]),"=r"((r)[2]),"=r"((r)[3]) : "r"(addr))

#define MMA_BF16(d, a, b0, b1) \
    asm volatile("mma.sync.aligned.m16n8k16.row.col.f32.bf16.bf16.f32 " \
        "{%0,%1,%2,%3}, {%4,%5,%6,%7}, {%8,%9}, {%0,%1,%2,%3};" \
        : "+f"((d)[0]),"+f"((d)[1]),"+f"((d)[2]),"+f"((d)[3]) \
        : "r"((a)[0]),"r"((a)[1]),"r"((a)[2]),"r"((a)[3]), "r"(b0),"r"(b1))

union BF2U { __nv_bfloat162 b; uint32_t u; };

__device__ __forceinline__ void split2(float x, float y, uint32_t& h, uint32_t& l) {
    BF2U hh, ll;
    hh.b = __floats2bfloat162_rn(x, y);
    float2 hf = __bfloat1622float2(hh.b);
    ll.b = __floats2bfloat162_rn(x - hf.x, y - hf.y);
    h = hh.u; l = ll.u;
}

// =====================================================================
// Kernel 1: QKV projection (R1 FFMA verbatim — proven exact)
// =====================================================================
__global__ __launch_bounds__(256) void qkv_gemm(
    const float* __restrict__ hs,
    const float* __restrict__ Wq, const float* __restrict__ bq,
    const float* __restrict__ Wk, const float* __restrict__ bk,
    const float* __restrict__ Wv, const float* __restrict__ bv)
{
    __shared__ float As[16][132];
    __shared__ float Bs[16][132];
    const int which = blockIdx.z;
    const float* W    = (which == 0) ? Wq : (which == 1) ? Wk : Wv;
    const float* bias = (which == 0) ? bq : (which == 1) ? bk : bv;
    float* out        = (which == 0) ? g_q : (which == 1) ? g_k : g_v;
    const float scale = (which == 0) ? 0.125f : 1.0f;

    const int tid = threadIdx.x;
    const int tx = tid & 15, ty = tid >> 4;
    const int m0 = blockIdx.y * 128, n0 = blockIdx.x * 128;

    float acc[8][8];
#pragma unroll
    for (int r = 0; r < 8; r++)
#pragma unroll
        for (int c = 0; c < 8; c++) acc[r][c] = 0.f;

    for (int kt = 0; kt < 512; kt += 16) {
#pragma unroll
        for (int i = 0; i < 2; i++) {
            int l = tid + i * 256;
            int row = l >> 2, kq = l & 3;
            float4 a = *(const float4*)&hs[(size_t)(m0 + row) * 512 + kt + kq * 4];
            As[kq*4+0][row] = a.x; As[kq*4+1][row] = a.y;
            As[kq*4+2][row] = a.z; As[kq*4+3][row] = a.w;
            float4 b = *(const float4*)&W[(size_t)(n0 + row) * 512 + kt + kq * 4];
            Bs[kq*4+0][row] = b.x; Bs[kq*4+1][row] = b.y;
            Bs[kq*4+2][row] = b.z; Bs[kq*4+3][row] = b.w;
        }
        __syncthreads();
#pragma unroll
        for (int k = 0; k < 16; k++) {
            float4 a0 = *(const float4*)&As[k][ty*8];
            float4 a1 = *(const float4*)&As[k][ty*8+4];
            float4 b0 = *(const float4*)&Bs[k][tx*8];
            float4 b1 = *(const float4*)&Bs[k][tx*8+4];
            float ar[8] = {a0.x,a0.y,a0.z,a0.w,a1.x,a1.y,a1.z,a1.w};
            float br[8] = {b0.x,b0.y,b0.z,b0.w,b1.x,b1.y,b1.z,b1.w};
#pragma unroll
            for (int r = 0; r < 8; r++)
#pragma unroll
                for (int c = 0; c < 8; c++)
                    acc[r][c] = fmaf(ar[r], br[c], acc[r][c]);
        }
        __syncthreads();
    }

    const int n = n0 + tx * 8;
    const int h = n >> 6, d0 = n & 63;
#pragma unroll
    for (int r = 0; r < 8; r++) {
        int m = m0 + ty * 8 + r;
        int b = m >> 11, t = m & 2047;
        float* orow = &out[(size_t)(((b << 3) + h) * 2048 + t) * 64 + d0];
        float4 o0, o1;
        o0.x = (acc[r][0] + bias[n+0]) * scale;
        o0.y = (acc[r][1] + bias[n+1]) * scale;
        o0.z = (acc[r][2] + bias[n+2]) * scale;
        o0.w = (acc[r][3] + bias[n+3]) * scale;
        o1.x = (acc[r][4] + bias[n+4]) * scale;
        o1.y = (acc[r][5] + bias[n+5]) * scale;
        o1.z = (acc[r][6] + bias[n+6]) * scale;
        o1.w = (acc[r][7] + bias[n+7]) * scale;
        *(float4*)&orow[0] = o0;
        *(float4*)&orow[4] = o1;
    }
}

// =====================================================================
// Kernel 1b: bf16 hi/lo split of q (prefilter operand prep)
// =====================================================================
__global__ __launch_bounds__(256) void qsplit_kernel()
{
    int i = blockIdx.x * 256 + threadIdx.x;   // over float4s, 1,048,576
    float4 v = ((const float4*)g_q)[i];
    uint2 hu, lu;
    split2(v.x, v.y, hu.x, lu.x);
    split2(v.z, v.w, hu.y, lu.y);
    ((uint2*)g_qh)[i] = hu;
    ((uint2*)g_ql)[i] = lu;
}

// =====================================================================
// Kernel 2: gather sampled keys -> packed fp32 + bf16 hi/lo
// =====================================================================
__global__ __launch_bounds__(256) void gather_kernel(const int* __restrict__ idx)
{
    const int bh = blockIdx.x, jb = blockIdx.y, tid = threadIdx.x;
#pragma unroll 4
    for (int it = 0; it < 16; it++) {
        int l = it * 256 + tid;
        int jl = l >> 4, q4 = l & 15;
        int j = jb * 256 + jl;
        int ti = idx[j];
        size_t dsto = (size_t)(bh * 2048 + j) * 64 + q4 * 4;
        float4 kv = *(const float4*)&g_k[(size_t)(bh * 2048 + ti) * 64 + q4 * 4];
        *(float4*)&g_ks[dsto] = kv;
        uint2 hu, lu;
        split2(kv.x, kv.y, hu.x, lu.x);
        split2(kv.z, kv.w, hu.y, lu.y);
        *(uint2*)&g_kh[dsto] = hu;
        *(uint2*)&g_kl[dsto] = lu;
    }
}

// =====================================================================
// Kernel 3: ksum and vmean (R1 verbatim)
// =====================================================================
__global__ void stats_kernel()
{
    const int bh = blockIdx.x, d = threadIdx.x;
    if (blockIdx.y == 0) {
        float s = 0.f;
        for (int j = 0; j < 2048; j++) s += g_ks[(size_t)(bh * 2048 + j) * 64 + d];
        g_ksum[bh * 64 + d] = s;
    } else {
        float s = 0.f;
        for (int j = 0; j < 2048; j++) s += g_v[(size_t)(bh * 2048 + j) * 64 + d];
        g_vmean[bh * 64 + d] = s * (1.0f / 2048.0f);
    }
}

// =====================================================================
// Kernel 4: APPROXIMATE sparsity via bf16 2-split 3-term mma.sync.
// Only used to pick rescue candidates — bounded error ~1e-3 << delta.
// =====================================================================
__global__ __launch_bounds__(256) void sparsity_mma()
{
    extern __shared__ __align__(16) __nv_bfloat16 dynsm[];
    __nv_bfloat16* Qh = dynsm;                 // [128][72]
    __nv_bfloat16* Ql = dynsm + 9216;
    __nv_bfloat16* Kh = dynsm + 18432;
    __nv_bfloat16* Kl = dynsm + 27648;
    float* red = (float*)(dynsm + 36864);      // [2][128]

    const int tid = threadIdx.x, wid = tid >> 5, lane = tid & 31;
    const int wm = wid >> 1, wn = wid & 1;
    const int m0 = blockIdx.x * 128, bh = blockIdx.y;

    const __nv_bfloat16* gqh = g_qh + (size_t)bh * TT * TD;
    const __nv_bfloat16* gql = g_ql + (size_t)bh * TT * TD;
    const __nv_bfloat16* gkh = g_kh + (size_t)bh * TT * TD;
    const __nv_bfloat16* gkl = g_kl + (size_t)bh * TT * TD;

#pragma unroll
    for (int i = 0; i < 4; i++) {
        int l = tid + i * 256;
        int row = l >> 3, seg = l & 7;
        *(uint4*)&Qh[row*72 + seg*8] = *(const uint4*)&gqh[(size_t)(m0+row)*64 + seg*8];
        *(uint4*)&Ql[row*72 + seg*8] = *(const uint4*)&gql[(size_t)(m0+row)*64 + seg*8];
    }

    const int arow = wm * 32 + (lane & 15);
    const int acol8 = (lane >> 4) << 3;
    const int brow = wn * 64 + (lane & 7) + ((lane >> 4) << 3);
    const int bk8 = ((lane >> 3) & 1) << 3;

    float rmax[2][2];
    rmax[0][0] = rmax[0][1] = rmax[1][0] = rmax[1][1] = -INFINITY;

    for (int nt = 0; nt < 16; nt++) {
        __syncthreads();
        const size_t n0 = (size_t)nt * 128;
#pragma unroll
        for (int i = 0; i < 4; i++) {
            int l = tid + i * 256;
            int row = l >> 3, seg = l & 7;
            *(uint4*)&Kh[row*72 + seg*8] = *(const uint4*)&gkh[(n0+row)*64 + seg*8];
            *(uint4*)&Kl[row*72 + seg*8] = *(const uint4*)&gkl[(n0+row)*64 + seg*8];
        }
        __syncthreads();

        float acc[2][8][4];
#pragma unroll
        for (int a = 0; a < 2; a++)
#pragma unroll
            for (int b = 0; b < 8; b++)
#pragma unroll
                for (int c = 0; c < 4; c++) acc[a][b][c] = 0.f;

#pragma unroll
        for (int kc = 0; kc < 64; kc += 16) {
            uint32_t ah[2][4], al[2][4];
#pragma unroll
            for (int mi = 0; mi < 2; mi++) {
                LDSM_X4(ah[mi], smem_u32(&Qh[(arow + mi*16)*72 + kc + acol8]));
                LDSM_X4(al[mi], smem_u32(&Ql[(arow + mi*16)*72 + kc + acol8]));
            }
#pragma unroll
            for (int nb = 0; nb < 4; nb++) {
                uint32_t bh4[4], bl4[4];
                LDSM_X4(bh4, smem_u32(&Kh[(brow + nb*16)*72 + kc + bk8]));
                LDSM_X4(bl4, smem_u32(&Kl[(brow + nb*16)*72 + kc + bk8]));
#pragma unroll
                for (int mi = 0; mi < 2; mi++) {
                    MMA_BF16(acc[mi][nb*2+0], ah[mi], bh4[0], bh4[1]);
                    MMA_BF16(acc[mi][nb*2+1], ah[mi], bh4[2], bh4[3]);
                    MMA_BF16(acc[mi][nb*2+0], ah[mi], bl4[0], bl4[1]);
                    MMA_BF16(acc[mi][nb*2+1], ah[mi], bl4[2], bl4[3]);
                    MMA_BF16(acc[mi][nb*2+0], al[mi], bh4[0], bh4[1]);
                    MMA_BF16(acc[mi][nb*2+1], al[mi], bh4[2], bh4[3]);
                }
            }
        }
#pragma unroll
        for (int mi = 0; mi < 2; mi++)
#pragma unroll
            for (int nf = 0; nf < 8; nf++) {
                rmax[mi][0] = fmaxf(rmax[mi][0], fmaxf(acc[mi][nf][0], acc[mi][nf][1]));
                rmax[mi][1] = fmaxf(rmax[mi][1], fmaxf(acc[mi][nf][2], acc[mi][nf][3]));
            }
    }

#pragma unroll
    for (int mi = 0; mi < 2; mi++)
#pragma unroll
        for (int hf = 0; hf < 2; hf++) {
            float v = rmax[mi][hf];
            v = fmaxf(v, __shfl_xor_sync(0xffffffff, v, 1));
            v = fmaxf(v, __shfl_xor_sync(0xffffffff, v, 2));
            if ((lane & 3) == 0)
                red[wn * 128 + wm * 32 + mi * 16 + hf * 8 + (lane >> 2)] = v;
        }
    __syncthreads();

    if (tid < 128) {
        float m = fmaxf(red[tid], red[128 + tid]);
        const float* qr = g_q + ((size_t)bh * TT + m0 + tid) * 64;
        const float* ks = g_ksum + bh * 64;
        float dot = 0.f;
#pragma unroll
        for (int d = 0; d < 64; d++) dot = fmaf(qr[d], ks[d], dot);
        g_sp[bh * TT + m0 + tid] = m - dot * (1.0f / 2048.0f);
    }
}

// =====================================================================
// Kernel 5: find approx 40th-largest sparsity per bh
// =====================================================================
__global__ __launch_bounds__(256) void topk40_kernel()
{
    __shared__ float sp[2048];
    __shared__ float rv[256];
    __shared__ int   ri[256];
    const int bh = blockIdx.x, tid = threadIdx.x;
    for (int l = tid; l < 2048; l += 256) sp[l] = g_sp[bh * 2048 + l];
    __syncthreads();
    for (int it = 0; it < TU; it++) {
        float bv = -INFINITY; int bi = 2048;
        for (int l = tid; l < 2048; l += 256) {
            float v = sp[l];
            if (v > bv) { bv = v; bi = l; }
        }
        rv[tid] = bv; ri[tid] = bi;
        __syncthreads();
        for (int s = 128; s > 0; s >>= 1) {
            if (tid < s) {
                float ov = rv[tid + s]; int oi = ri[tid + s];
                if (ov > rv[tid] || (ov == rv[tid] && oi < ri[tid])) { rv[tid] = ov; ri[tid] = oi; }
            }
            __syncthreads();
        }
        if (tid == 0) {
            sp[ri[0]] = -INFINITY;
            if (it == TU - 1) g_s40[bh] = rv[0];
        }
        __syncthreads();
    }
}

// =====================================================================
// Kernel 5b: collect candidates with approx score >= s40 - delta
// =====================================================================
__global__ __launch_bounds__(256) void cand_kernel()
{
    __shared__ int cnt;
    const int bh = blockIdx.x, tid = threadIdx.x;
    if (tid == 0) cnt = 0;
    __syncthreads();
    const float thr = g_s40[bh] - 0.02f;
    for (int l = tid; l < 2048; l += 256) {
        if (g_sp[bh * 2048 + l] >= thr) {
            int p = atomicAdd(&cnt, 1);
            if (p < TCAP) g_cand[bh * TCAP + p] = l;
        }
    }
    __syncthreads();
    if (tid == 0) g_ncand[bh] = (cnt < TCAP) ? cnt : TCAP;
}

// =====================================================================
// Kernel 5c: exact fp32 rescore of candidates (partial rowmax / 256 keys)
// fmaf order identical to R1's sparsity_kernel -> bit-identical dots.
// =====================================================================
__global__ __launch_bounds__(256) void rescore_kernel()
{
    __shared__ float qc[64][68];
    __shared__ float ks[32][68];
    const int bh = blockIdx.x, sp = blockIdx.y, tid = threadIdx.x;
    const int ncand = g_ncand[bh];
    const int c = tid >> 2, l4 = tid & 3;

    for (int c0 = 0; c0 < ncand; c0 += 64) {
        const int nc = min(64, ncand - c0);
        __syncthreads();
        for (int l = tid; l < nc * 16; l += 256) {
            int cc = l >> 4, q4 = l & 15;
            int t = g_cand[bh * TCAP + c0 + cc];
            *(float4*)&qc[cc][q4*4] = *(const float4*)&g_q[((size_t)bh * 2048 + t) * 64 + q4 * 4];
        }
        float m = -INFINITY;
        for (int ch = 0; ch < 8; ch++) {
            const int j0 = sp * 256 + ch * 32;
            __syncthreads();
            for (int l = tid; l < 512; l += 256) {
                int j = l >> 4, q4 = l & 15;
                *(float4*)&ks[j][q4*4] = *(const float4*)&g_ks[((size_t)bh * 2048 + j0 + j) * 64 + q4 * 4];
            }
            __syncthreads();
            if (c < nc) {
#pragma unroll
                for (int kk = 0; kk < 8; kk++) {
                    int j = l4 + kk * 4;
                    float dot = 0.f;
#pragma unroll
                    for (int d = 0; d < 64; d++) dot = fmaf(qc[c][d], ks[j][d], dot);
                    m = fmaxf(m, dot);
                }
            }
        }
        m = fmaxf(m, __shfl_xor_sync(0xffffffff, m, 1));
        m = fmaxf(m, __shfl_xor_sync(0xffffffff, m, 2));
        if (l4 == 0 && c < nc)
            g_rmax[(bh * TCAP + c0 + c) * NSPLIT + sp] = m;
    }
}

// =====================================================================
// Kernel 5d: exact sparsity of candidates + exact top-40 (tie: lower t)
// =====================================================================
__global__ __launch_bounds__(256) void final_topk_kernel()
{
    __shared__ float sv[256];
    __shared__ int   st[256];
    __shared__ float rv[256];
    __shared__ int   rs[256];
    __shared__ float sks[64];
    const int bh = blockIdx.x, tid = threadIdx.x;
    const int ncand = g_ncand[bh];
    if (tid < 64) sks[tid] = g_ksum[bh * 64 + tid];
    __syncthreads();

    float val = -INFINITY;
    int t = 0x7fffffff;
    if (tid < ncand) {
        t = g_cand[bh * TCAP + tid];
        float m = -INFINITY;
#pragma unroll
        for (int sp = 0; sp < NSPLIT; sp++)
            m = fmaxf(m, g_rmax[(bh * TCAP + tid) * NSPLIT + sp]);
        const float* qr = g_q + ((size_t)bh * 2048 + t) * 64;
        float dot = 0.f;
#pragma unroll
        for (int d = 0; d < 64; d++) dot = fmaf(qr[d], sks[d], dot);
        val = m - dot * (1.0f / 2048.0f);
    }
    sv[tid] = val; st[tid] = t;
    __syncthreads();

    for (int it = 0; it < TU; it++) {
        rv[tid] = sv[tid]; rs[tid] = tid;
        __syncthreads();
        for (int s = 128; s > 0; s >>= 1) {
            if (tid < s) {
                float ov = rv[tid + s]; int os = rs[tid + s];
                if (ov > rv[tid] || (ov == rv[tid] && st[os] < st[rs[tid]])) { rv[tid] = ov; rs[tid] = os; }
            }
            __syncthreads();
        }
        if (tid == 0) { g_top[bh * TU + it] = st[rs[0]]; sv[rs[0]] = -INFINITY; }
        __syncthreads();
    }
}

// =====================================================================
// Kernel 6: scores = q_reduce @ k^T (R1 verbatim)
// =====================================================================
__global__ __launch_bounds__(256) void scores_kernel()
{
    __shared__ float qs[40][68];
    __shared__ float ks[128][68];
    const int nt = blockIdx.x, bh = blockIdx.y, tid = threadIdx.x;
    const int n0 = nt * 128;
    for (int l = tid; l < 640; l += 256) {
        int i = l >> 4, q4 = l & 15;
        int t = g_top[bh * TU + i];
        *(float4*)&qs[i][q4*4] = *(const float4*)&g_q[((size_t)bh * 2048 + t) * 64 + q4 * 4];
    }
    for (int l = tid; l < 2048; l += 256) {
        int j = l >> 4, q4 = l & 15;
        *(float4*)&ks[j][q4*4] = *(const float4*)&g_k[((size_t)bh * 2048 + n0 + j) * 64 + q4 * 4];
    }
    __syncthreads();
    const int j = tid & 127;
    const int i0 = (tid >> 7) * 20;
    for (int i = i0; i < i0 + 20; i++) {
        float dot = 0.f;
#pragma unroll
        for (int d = 0; d < 64; d++) dot = fmaf(qs[i][d], ks[j][d], dot);
        g_sc[((size_t)bh * TU + i) * 2048 + n0 + j] = dot;
    }
}

// =====================================================================
// Kernel 7: row softmax (R1 verbatim)
// =====================================================================
__global__ __launch_bounds__(256) void softmax_kernel()
{
    __shared__ float red[256];
    const int row = blockIdx.x, tid = threadIdx.x;
    float* p = g_sc + (size_t)row * 2048;
    float m = -INFINITY;
    for (int l = tid; l < 2048; l += 256) m = fmaxf(m, p[l]);
    red[tid] = m; __syncthreads();
    for (int s = 128; s > 0; s >>= 1) { if (tid < s) red[tid] = fmaxf(red[tid], red[tid + s]); __syncthreads(); }
    m = red[0]; __syncthreads();
    float sum = 0.f;
    for (int l = tid; l < 2048; l += 256) {
        float e = expf(p[l] - m);
        p[l] = e;
        sum += e;
    }
    red[tid] = sum; __syncthreads();
    for (int s = 128; s > 0; s >>= 1) { if (tid < s) red[tid] += red[tid + s]; __syncthreads(); }
    const float inv = 1.0f / red[0];
    for (int l = tid; l < 2048; l += 256) p[l] *= inv;
}

// =====================================================================
// Kernel 8: attn_out partials = probs @ v (R1 verbatim)
// =====================================================================
__global__ __launch_bounds__(256) void pv_kernel()
{
    __shared__ float vs[64][68];
    __shared__ float ps[40][68];
    const int sp = blockIdx.x, bh = blockIdx.y, tid = threadIdx.x;
    const int d = tid & 63, ig = tid >> 6;
    float acc[10];
#pragma unroll
    for (int s = 0; s < 10; s++) acc[s] = 0.f;
    for (int c = 0; c < 4; c++) {
        const int j0 = sp * 256 + c * 64;
        for (int l = tid; l < 1024; l += 256) {
            int j = l >> 4, q4 = l & 15;
            *(float4*)&vs[j][q4*4] = *(const float4*)&g_v[((size_t)bh * 2048 + j0 + j) * 64 + q4 * 4];
        }
        for (int l = tid; l < 640; l += 256) {
            int i = l >> 4, q4 = l & 15;
            *(float4*)&ps[i][q4*4] = *(const float4*)&g_sc[((size_t)bh * TU + i) * 2048 + j0 + q4 * 4];
        }
        __syncthreads();
#pragma unroll 4
        for (int jj = 0; jj < 64; jj++) {
            float vv = vs[jj][d];
#pragma unroll
            for (int s = 0; s < 10; s++)
                acc[s] = fmaf(ps[ig * 10 + s][jj], vv, acc[s]);
        }
        __syncthreads();
    }
#pragma unroll
    for (int s = 0; s < 10; s++)
        g_part[((size_t)(bh * NSPLIT + sp) * TU + ig * 10 + s) * 64 + d] = acc[s];
}

// =====================================================================
// Kernel 9: fill merged context with vmean (R1 verbatim)
// =====================================================================
__global__ __launch_bounds__(256) void ctxfill_kernel()
{
    const int idx = blockIdx.x * 256 + threadIdx.x;
    const int m = idx >> 7, nf4 = idx & 127;
    const int b = m >> 11;
    const int h = nf4 >> 4, d0 = (nf4 & 15) * 4;
    float4 v = *(const float4*)&g_vmean[((b << 3) + h) * 64 + d0];
    *(float4*)&g_ctx[(size_t)m * 512 + nf4 * 4] = v;
}

// =====================================================================
// Kernel 10: reduce attn partials + scatter (R1 verbatim)
// =====================================================================
__global__ void scatter_kernel()
{
    const int bh = blockIdx.x, i = blockIdx.y, d = threadIdx.x;  // 64 threads
    const int t = g_top[bh * TU + i];
    float s = 0.f;
#pragma unroll
    for (int sp = 0; sp < NSPLIT; sp++)
        s += g_part[((size_t)(bh * NSPLIT + sp) * TU + i) * 64 + d];
    const int b = bh >> 3, h = bh & 7;
    g_ctx[(size_t)((b << 11) + t) * 512 + (h << 6) + d] = s;
}

// =====================================================================
// Kernel 11: output projection FFMA (R1 verbatim)
// =====================================================================
__global__ __launch_bounds__(256) void out_gemm(
    const float* __restrict__ Wo, const float* __restrict__ bo,
    float* __restrict__ out)
{
    __shared__ float As[16][132];
    __shared__ float Bs[16][132];
    const int tid = threadIdx.x;
    const int tx = tid & 15, ty = tid >> 4;
    const int m0 = blockIdx.y * 128, n0 = blockIdx.x * 128;

    float acc[8][8];
#pragma unroll
    for (int r = 0; r < 8; r++)
#pragma unroll
        for (int c = 0; c < 8; c++) acc[r][c] = 0.f;

    for (int kt = 0; kt < 512; kt += 16) {
#pragma unroll
        for (int i = 0; i < 2; i++) {
            int l = tid + i * 256;
            int row = l >> 2, kq = l & 3;
            float4 a = *(const float4*)&g_ctx[(size_t)(m0 + row) * 512 + kt + kq * 4];
            As[kq*4+0][row] = a.x; As[kq*4+1][row] = a.y;
            As[kq*4+2][row] = a.z; As[kq*4+3][row] = a.w;
            float4 b = *(const float4*)&Wo[(size_t)(n0 + row) * 512 + kt + kq * 4];
            Bs[kq*4+0][row] = b.x; Bs[kq*4+1][row] = b.y;
            Bs[kq*4+2][row] = b.z; Bs[kq*4+3][row] = b.w;
        }
        __syncthreads();
#pragma unroll
        for (int k = 0; k < 16; k++) {
            float4 a0 = *(const float4*)&As[k][ty*8];
            float4 a1 = *(const float4*)&As[k][ty*8+4];
            float4 b0 = *(const float4*)&Bs[k][tx*8];
            float4 b1 = *(const float4*)&Bs[k][tx*8+4];
            float ar[8] = {a0.x,a0.y,a0.z,a0.w,a1.x,a1.y,a1.z,a1.w};
            float br[8] = {b0.x,b0.y,b0.z,b0.w,b1.x,b1.y,b1.z,b1.w};
#pragma unroll
            for (int r = 0; r < 8; r++)
#pragma unroll
                for (int c = 0; c < 8; c++)
                    acc[r][c] = fmaf(ar[r], br[c], acc[r][c]);
        }
        __syncthreads();
    }

    const int n = n0 + tx * 8;
#pragma unroll
    for (int r = 0; r < 8; r++) {
        int m = m0 + ty * 8 + r;
        float4 o0, o1;
        o0.x = acc[r][0] + bo[n+0]; o0.y = acc[r][1] + bo[n+1];
        o0.z = acc[r][2] + bo[n+2]; o0.w = acc[r][3] + bo[n+3];
        o1.x = acc[r][4] + bo[n+4]; o1.y = acc[r][5] + bo[n+5];
        o1.z = acc[r][6] + bo[n+6]; o1.w = acc[r][7] + bo[n+7];
        *(float4*)&out[(size_t)m * 512 + n]     = o0;
        *(float4*)&out[(size_t)m * 512 + n + 4] = o1;
    }
}

// =====================================================================
extern "C" void kernel_launch(void* const* d_in, const int* in_sizes, int n_in,
                              void* d_out, int out_size)
{
    const float* hs = (const float*)d_in[0];
    const int*  idx = (const int*)  d_in[1];
    const float* Wq = (const float*)d_in[2]; const float* bq = (const float*)d_in[3];
    const float* Wk = (const float*)d_in[4]; const float* bk = (const float*)d_in[5];
    const float* Wv = (const float*)d_in[6]; const float* bv = (const float*)d_in[7];
    const float* Wo = (const float*)d_in[8]; const float* bo = (const float*)d_in[9];
    float* out = (float*)d_out;

    cudaFuncSetAttribute(sparsity_mma, cudaFuncAttributeMaxDynamicSharedMemorySize, 75776);

    qkv_gemm     <<<dim3(4, 64, 3), 256>>>(hs, Wq, bq, Wk, bk, Wv, bv);
    qsplit_kernel<<<4096, 256>>>();
    gather_kernel<<<dim3(32, 8), 256>>>(idx);
    stats_kernel <<<dim3(32, 2), 64>>>();
    sparsity_mma <<<dim3(16, 32), 256, 75776>>>();
    topk40_kernel<<<32, 256>>>();
    cand_kernel  <<<32, 256>>>();
    rescore_kernel<<<dim3(32, NSPLIT), 256>>>();
    final_topk_kernel<<<32, 256>>>();
    scores_kernel<<<dim3(16, 32), 256>>>();
    softmax_kernel<<<TBH * TU, 256>>>();
    pv_kernel    <<<dim3(NSPLIT, 32), 256>>>();
    ctxfill_kernel<<<4096, 256>>>();
    scatter_kernel<<<dim3(32, TU), 64>>>();
    out_gemm     <<<dim3(4, 64), 256>>>(Wo, bo, out);
}